// round 13
// baseline (speedup 1.0000x reference)
#include <cuda_runtime.h>
#include <math.h>
#include <stdint.h>

#define MAXB    64
#define MAXP    8732
#define MAXBP   (MAXB * MAXP)
#define MAXG    16
#define TILE    256
#define SM_ROWS 64
#define MAXNBLK 140

// ---------------- scratch (static device globals; zero-initialized) -------------
__device__ unsigned      g_negkey[MAXBP];
__device__ unsigned long long g_bestkey[MAXB * MAXG];    // reset by K2
__device__ float g_part_ce[MAXB * MAXNBLK];
__device__ float g_part_box[MAXB * MAXNBLK];
__device__ int   g_part_np[MAXB * MAXNBLK];
__device__ float g_batch_cls[MAXB];
__device__ float g_batch_box[MAXB];
__device__ int   g_batch_np[MAXB];
__device__ int   g_done;

__device__ __forceinline__ unsigned smem_u32(const void* p) {
    unsigned a;
    asm("{ .reg .u64 t; cvta.to.shared.u64 t, %1; cvt.u32.u64 %0, t; }"
        : "=r"(a) : "l"(p));
    return a;
}

// Canonical base-match: MUST be identical everywhere it is used.
__device__ __forceinline__ void base_match(
    float4 pv, const float* gx0, const float* gy0,
    const float* gx1, const float* gy1, const float* ga, int G,
    float& mval, int& mg)
{
    float px0 = pv.x - 0.5f * pv.z, py0 = pv.y - 0.5f * pv.w;
    float px1 = pv.x + 0.5f * pv.z, py1 = pv.y + 0.5f * pv.w;
    float parea = (px1 - px0) * (py1 - py0);
    mval = -1.0f; mg = 0;
#pragma unroll
    for (int g = 0; g < MAXG; g++) {
        if (g >= G) break;
        float ix0 = fmaxf(gx0[g], px0), iy0 = fmaxf(gy0[g], py0);
        float ix1 = fminf(gx1[g], px1), iy1 = fminf(gy1[g], py1);
        float iw = fmaxf(ix1 - ix0, 0.0f), ih = fmaxf(iy1 - iy0, 0.0f);
        float inter = iw * ih;
        float iou = inter / (ga[g] + parea - inter);      // IEEE div (matches ref)
        if (iou > mval) { mval = iou; mg = g; }           // first-g tie-break
    }
}

__device__ __forceinline__ float smooth_l1_box(
    float4 pv, float4 br, float bx0, float by0, float bx1, float by1)
{
    float t0 = ((bx0 + bx1) * 0.5f - pv.x) / (0.1f * pv.z);
    float t1 = ((by0 + by1) * 0.5f - pv.y) / (0.1f * pv.w);
    float t2 = __logf((bx1 - bx0) / pv.z) / 0.2f;
    float t3 = __logf((by1 - by0) / pv.w) / 0.2f;
    float d0 = fabsf(br.x - t0), d1 = fabsf(br.y - t1);
    float d2 = fabsf(br.z - t2), d3 = fabsf(br.w - t3);
    float s  = (d0 < 1.0f) ? 0.5f * d0 * d0 : d0 - 0.5f;
    s += (d1 < 1.0f) ? 0.5f * d1 * d1 : d1 - 0.5f;
    s += (d2 < 1.0f) ? 0.5f * d2 * d2 : d2 - 0.5f;
    s += (d3 < 1.0f) ? 0.5f * d3 * d3 : d3 - 0.5f;
    return s;
}

// =====================================================================
// K1: heterogeneous kernel.  Match role (bestkey only) 1-in-4
// interleaved with softmax+apply role (TMA-staged, self-contained:
// recomputes its own rows' IoU argmax during TMA flight).
// =====================================================================
__global__ __launch_bounds__(256) void fused_ms(
    const float* __restrict__ logits,
    const float* __restrict__ priors,
    const float* __restrict__ box_reg,
    const float* __restrict__ gt_boxes,
    const int*   __restrict__ gt_labels,
    int P, int C, int G, int nMatch, int nTiles, int nblk)
{
    __shared__ float4 sbuf4[SM_ROWS * 81 / 4];    // softmax stage / match iou tile
    __shared__ float gx0[MAXG], gy0[MAXG], gx1[MAXG], gy1[MAXG], ga[MAXG];
    __shared__ int   glab[MAXG];
    __shared__ int   s_lab[SM_ROWS];
    __shared__ float s_box[SM_ROWS];
    __shared__ float wce[8];
    __shared__ unsigned long long mbar;

    const int tid = threadIdx.x;
    const int bid = blockIdx.x;
    const int lane = tid & 31, warp = tid >> 5;
    const bool isMatch = ((bid & 3) == 0) && ((bid >> 2) < nMatch);

    if (isMatch) {
        // ---------------- match role: per-GT best prior over 256 priors ----
        const int mi = bid >> 2;
        const int b = mi / nTiles;
        const int t = mi % nTiles;
        unsigned* siou = (unsigned*)sbuf4;        // [16][TILE] iou bits

        if (tid < G) {
            float4 gv = __ldg((const float4*)gt_boxes + b * G + tid);
            gx0[tid] = gv.x; gy0[tid] = gv.y; gx1[tid] = gv.z; gy1[tid] = gv.w;
            ga[tid]  = (gv.z - gv.x) * (gv.w - gv.y);
        }
        __syncthreads();

        const int p0 = t * TILE;
        const int p  = p0 + tid;

        if (p < P) {
            float4 pv = __ldg((const float4*)priors + p);
            float px0 = pv.x - 0.5f * pv.z, py0 = pv.y - 0.5f * pv.w;
            float px1 = pv.x + 0.5f * pv.z, py1 = pv.y + 0.5f * pv.w;
            float parea = (px1 - px0) * (py1 - py0);
#pragma unroll
            for (int g = 0; g < MAXG; g++) {
                if (g >= G) break;
                float ix0 = fmaxf(gx0[g], px0), iy0 = fmaxf(gy0[g], py0);
                float ix1 = fminf(gx1[g], px1), iy1 = fminf(gy1[g], py1);
                float iw = fmaxf(ix1 - ix0, 0.0f), ih = fmaxf(iy1 - iy0, 0.0f);
                float inter = iw * ih;
                float iou = inter / (ga[g] + parea - inter); // IEEE div
                siou[g * TILE + tid] = __float_as_uint(iou); // iou>=0 ordered bits
            }
        } else {
#pragma unroll
            for (int g = 0; g < MAXG; g++) {
                if (g >= G) break;
                siou[g * TILE + tid] = 0u;
            }
        }
        __syncthreads();

#pragma unroll
        for (int gg = warp; gg < MAXG; gg += 8) {
            if (gg >= G) break;
            unsigned long long best = 0ull;
#pragma unroll
            for (int i = 0; i < TILE / 32; i++) {
                const int c = lane + 32 * i;
                unsigned bits = siou[gg * TILE + c];
                unsigned long long key =
                    ((unsigned long long)bits << 32) |
                    (unsigned long long)(0xFFFFFFFFu - (unsigned)(p0 + c));
                if (key > best) best = key;                  // lower p wins ties
            }
#pragma unroll
            for (int o = 16; o > 0; o >>= 1) {
                unsigned long long other = __shfl_down_sync(0xffffffffu, best, o);
                if (other > best) best = other;
            }
            if (lane == 0) atomicMax(&g_bestkey[b * MAXG + gg], best);
        }
    } else {
        // -------------- softmax+apply role: 64 rows, TMA staged ------------
        const int nm_before = min((bid + 3) >> 2, nMatch);
        const int r  = bid - nm_before;
        const int b  = r / nblk;
        const int bx = r % nblk;
        const int r0 = bx * SM_ROWS;
        const int R  = min(SM_ROWS, P - r0);

        const float* base = logits + ((size_t)b * P + r0) * C;
        const unsigned nbytes = (unsigned)(R * C * 4);       // 16B multiple

        const unsigned mb_addr = smem_u32(&mbar);
        const unsigned dst     = smem_u32(sbuf4);
        if (tid == 0) {
            asm volatile("mbarrier.init.shared.b64 [%0], %1;"
                         :: "r"(mb_addr), "r"(1) : "memory");
        }
        __syncthreads();
        if (tid == 0) {
            asm volatile("mbarrier.arrive.expect_tx.shared.b64 _, [%0], %1;"
                         :: "r"(mb_addr), "r"(nbytes) : "memory");
            asm volatile(
                "cp.async.bulk.shared::cta.global.mbarrier::complete_tx::bytes "
                "[%0], [%1], %2, [%3];"
                :: "r"(dst), "l"(base), "r"(nbytes), "r"(mb_addr) : "memory");
        }

        // ---- pre-pass while TMA is in flight: recompute base match ----
        if (tid < G) {
            float4 gv = __ldg((const float4*)gt_boxes + b * G + tid);
            gx0[tid] = gv.x; gy0[tid] = gv.y; gx1[tid] = gv.z; gy1[tid] = gv.w;
            ga[tid]  = (gv.z - gv.x) * (gv.w - gv.y);
            glab[tid] = gt_labels[b * G + tid];
        }
        __syncthreads();
        if (tid < R) {
            const int p = r0 + tid;
            float4 pv = __ldg((const float4*)priors + p);
            float mval; int mg;
            base_match(pv, gx0, gy0, gx1, gy1, ga, G, mval, mg);
            if (mval >= 0.5f) {
                s_lab[tid] = glab[mg];
                float4 br = __ldg((const float4*)box_reg + (b * P + p));
                s_box[tid] = smooth_l1_box(pv, br, gx0[mg], gy0[mg],
                                           gx1[mg], gy1[mg]);
            } else {
                s_lab[tid] = 0;
                s_box[tid] = 0.0f;
            }
        }

        // wait for TMA completion
        {
            unsigned done;
            do {
                asm volatile(
                    "{\n\t.reg .pred p;\n\t"
                    "mbarrier.try_wait.parity.shared.b64 p, [%1], 0;\n\t"
                    "selp.b32 %0, 1, 0, p;\n\t}"
                    : "=r"(done) : "r"(mb_addr) : "memory");
            } while (!done);
        }
        __syncthreads();

        const float* sbuf = (const float*)sbuf4;
        float ce = 0.0f;
#pragma unroll
        for (int j = 0; j < SM_ROWS / 8; j++) {
            const int row = warp + j * 8;
            if (row >= R) break;
            const float* rp = sbuf + row * 81;
            float sum = 0.0f;
            if (lane      < C) sum += __expf(rp[lane]);
            if (lane + 32 < C) sum += __expf(rp[lane + 32]);
            if (lane + 64 < C) sum += __expf(rp[lane + 64]);
#pragma unroll
            for (int o = 16; o > 0; o >>= 1)
                sum += __shfl_xor_sync(0xffffffffu, sum, o);
            if (lane == 0) {
                float lse = __logf(sum);
                const int lab = s_lab[row];
                if (lab > 0) {
                    g_negkey[b * P + r0 + row] = 0u;
                    ce += lse - rp[lab];                      // smem gather
                } else {
                    g_negkey[b * P + r0 + row] =
                        __float_as_uint(fmaxf(lse - rp[0], 0.0f));
                }
            }
        }
        if (lane == 0) wce[warp] = ce;
        __syncthreads();

        if (warp == 0) {
            float boxv = 0.0f; int np = 0;
            if (lane < R)      { boxv += s_box[lane];      np += (s_lab[lane] > 0); }
            if (lane + 32 < R) { boxv += s_box[lane + 32]; np += (s_lab[lane + 32] > 0); }
#pragma unroll
            for (int o = 16; o > 0; o >>= 1) {
                boxv += __shfl_down_sync(0xffffffffu, boxv, o);
                np   += __shfl_down_sync(0xffffffffu, np, o);
            }
            if (lane == 0) {
                float c = 0.0f;
#pragma unroll
                for (int w2 = 0; w2 < 8; w2++) c += wce[w2];
                const int pi = b * nblk + bx;
                g_part_ce[pi]  = c;
                g_part_box[pi] = boxv;
                g_part_np[pi]  = np;
            }
        }
    }
}

// =====================================================================
// K2: per-batch override deltas (<=16) + exact top-k + finalize.
// =====================================================================
__global__ __launch_bounds__(1024) void topk_kernel(
    float* __restrict__ out,
    const float* __restrict__ logits,
    const float* __restrict__ priors,
    const float* __restrict__ box_reg,
    const float* __restrict__ gt_boxes,
    const int*   __restrict__ gt_labels,
    int P, int C, int G, int B, int nblk)
{
    const int b = blockIdx.x;
    const int tid = threadIdx.x;
    const int NT = 1024;
    const int lane = tid & 31, warp = tid >> 5;

    __shared__ unsigned sk[MAXP];
    __shared__ int   hist[4096];
    __shared__ int   suf[256];
    __shared__ float wsf[32], wsf2[32];
    __shared__ int   wsi[32];
    __shared__ float gx0[MAXG], gy0[MAXG], gx1[MAXG], gy1[MAXG], ga[MAXG];
    __shared__ int   glab[MAXG], bp[MAXG];
    __shared__ float d_ce[MAXG], d_box[MAXG];
    __shared__ int   d_np[MAXG];
    __shared__ int   f_bucket, f_above, sh_k, sh_last;
    __shared__ float sh_ce;

    // stage keys (batched, MLP=3)
    {
        const int nv = P >> 2;
        const uint4* nk4 = (const uint4*)(g_negkey + b * P);
        uint4 kv[3]; bool gd[3];
#pragma unroll
        for (int kk = 0; kk < 3; kk++) {
            const int i = tid + kk * NT;
            gd[kk] = i < nv;
            if (gd[kk]) kv[kk] = __ldg(&nk4[i]);
        }
#pragma unroll
        for (int kk = 0; kk < 3; kk++) {
            const int i = tid + kk * NT;
            if (gd[kk]) {
                sk[i * 4 + 0] = kv[kk].x; sk[i * 4 + 1] = kv[kk].y;
                sk[i * 4 + 2] = kv[kk].z; sk[i * 4 + 3] = kv[kk].w;
            }
        }
        for (int i = tid + 3 * NT; i < nv; i += NT) {
            uint4 v = __ldg(&nk4[i]);
            sk[i * 4 + 0] = v.x; sk[i * 4 + 1] = v.y;
            sk[i * 4 + 2] = v.z; sk[i * 4 + 3] = v.w;
        }
    }
    if (tid < G) {
        float4 gv = __ldg((const float4*)gt_boxes + b * G + tid);
        gx0[tid] = gv.x; gy0[tid] = gv.y; gx1[tid] = gv.z; gy1[tid] = gv.w;
        ga[tid]  = (gv.z - gv.x) * (gv.w - gv.y);
        glab[tid] = gt_labels[b * G + tid];
        unsigned long long k = g_bestkey[b * MAXG + tid];
        bp[tid] = (int)(0xFFFFFFFFu - (unsigned)(k & 0xFFFFFFFFull));
        g_bestkey[b * MAXG + tid] = 0ull;         // reset for next replay
        d_ce[tid] = 0.0f; d_box[tid] = 0.0f; d_np[tid] = 0;
    }
    __syncthreads();

    // ---- override deltas: winner g = LAST g with this p (matches .set) ----
    if (tid < G) {
        const int g = tid;
        const int p = bp[g];
        bool winner = true;
        for (int g2 = g + 1; g2 < G; g2++)
            if (bp[g2] == p) { winner = false; break; }
        if (winner) {
            float4 pv = __ldg((const float4*)priors + p);
            float mval; int mgb;
            base_match(pv, gx0, gy0, gx1, gy1, ga, G, mval, mgb);

            const int newlab = glab[g];
            float4 br = __ldg((const float4*)box_reg + (b * P + p));
            float box_new = smooth_l1_box(pv, br, gx0[g], gy0[g], gx1[g], gy1[g]);
            const float* rowp = logits + ((size_t)(b * P + p)) * C;
            float xnew = __ldg(rowp + newlab);

            if (mval >= 0.5f) {
                // base was positive with GT mgb (unless mgb == g: no-op)
                if (mgb != g) {
                    const int oldlab = glab[mgb];
                    float xold = __ldg(rowp + oldlab);
                    float box_old = smooth_l1_box(pv, br, gx0[mgb], gy0[mgb],
                                                  gx1[mgb], gy1[mgb]);
                    d_ce[g]  = xold - xnew;         // lse cancels
                    d_box[g] = box_new - box_old;
                } else if (newlab != glab[mgb]) {
                    // same GT index: labels identical, nothing to do
                }
            } else {
                // base was negative: promote
                float bg = __uint_as_float(sk[p]);  // = max(lse - x0, 0)
                float x0 = __ldg(rowp);
                sk[p] = 0u;                          // unique p across winners
                d_ce[g]  = bg + x0 - xnew;           // = lse - x[newlab]
                d_box[g] = box_new;
                d_np[g]  = 1;
            }
        }
    }
    __syncthreads();

    // ---- reduce block partials + deltas ----
    float ce = 0.0f, bx = 0.0f; int np = 0;
    for (int i = tid; i < nblk; i += NT) {
        ce += g_part_ce[b * nblk + i];
        bx += g_part_box[b * nblk + i];
        np += g_part_np[b * nblk + i];
    }
#pragma unroll
    for (int o = 16; o > 0; o >>= 1) {
        ce += __shfl_down_sync(0xffffffffu, ce, o);
        bx += __shfl_down_sync(0xffffffffu, bx, o);
        np += __shfl_down_sync(0xffffffffu, np, o);
    }
    if (lane == 0) { wsf[warp] = ce; wsf2[warp] = bx; wsi[warp] = np; }
    __syncthreads();
    if (tid == 0) {
        float c2 = 0.f, b2 = 0.f; int n2 = 0;
#pragma unroll
        for (int w2 = 0; w2 < 32; w2++) { c2 += wsf[w2]; b2 += wsf2[w2]; n2 += wsi[w2]; }
        for (int g = 0; g < G; g++) { c2 += d_ce[g]; b2 += d_box[g]; n2 += d_np[g]; }
        int k = n2 * 3; if (k > P) k = P;
        sh_k = k; sh_ce = c2;
        g_batch_box[b] = b2;
        g_batch_np[b]  = n2;
    }
    __syncthreads();
    int k = sh_k;

    // ---- exact top-k sum: 3-pass histogram select, warp-aggregated ----
    float cls = sh_ce;
    if (k > 0) {
        unsigned prefix = 0;
        const int shifts[3] = {20, 8, 0};
        const int bitsA[3]  = {12, 12, 8};
        const int iters = (P + NT - 1) / NT;
#pragma unroll
        for (int ps = 0; ps < 3; ps++) {
            const int shift = shifts[ps];
            const int nbits = bitsA[ps];
            const int nb = 1 << nbits;
            const unsigned himask = (unsigned)(~((1ull << (shift + nbits)) - 1ull));

            for (int i = tid; i < nb; i += NT) hist[i] = 0;
            __syncthreads();

            for (int it = 0; it < iters; it++) {
                const int p = tid + it * NT;
                unsigned key = (p < P) ? sk[p] : 0u;
                const bool act = (p < P) && ((key & himask) == prefix);
                unsigned bkt = act ? ((key >> shift) & (nb - 1)) : 0xFFFFFFFFu;
                unsigned mm = __match_any_sync(0xffffffffu, bkt);
                if (act && ((int)(__ffs(mm) - 1) == lane))
                    atomicAdd(&hist[bkt], __popc(mm));
            }
            __syncthreads();

            const int cw = nb >> 8;
            int cs = 0;
            if (tid < 256)
                for (int i = 0; i < cw; i++) cs += hist[tid * cw + i];
            int v = cs;
#pragma unroll
            for (int o = 1; o < 32; o <<= 1) {
                int u = __shfl_down_sync(0xffffffffu, v, o);
                if (lane + o < 32) v += u;
            }
            if (tid < 256 && lane == 0) wsi[warp] = v;
            __syncthreads();
            if (tid < 256) {
                int off = 0;
                for (int w2 = warp + 1; w2 < 8; w2++) off += wsi[w2];
                suf[tid] = v + off;                      // inclusive suffix
            }
            __syncthreads();
            if (tid < 256) {
                int running = suf[tid] - cs;             // strictly above chunk
                for (int i = cw - 1; i >= 0; i--) {
                    int c = hist[tid * cw + i];
                    if (c > 0 && running < k && running + c >= k) {
                        f_bucket = tid * cw + i;         // unique writer
                        f_above  = running;
                    }
                    running += c;
                }
            }
            __syncthreads();
            prefix |= ((unsigned)f_bucket) << shift;
            k -= f_above;
            __syncthreads();
        }

        float ss = 0.0f;
        for (int p = tid; p < P; p += NT) {
            unsigned key = sk[p];
            if (key > prefix) ss += __uint_as_float(key);
        }
#pragma unroll
        for (int o = 16; o > 0; o >>= 1) ss += __shfl_down_sync(0xffffffffu, ss, o);
        if (lane == 0) wsf[warp] = ss;
        __syncthreads();
        if (tid == 0) {
            float s2 = 0.f;
#pragma unroll
            for (int w2 = 0; w2 < 32; w2++) s2 += wsf[w2];
            wsf[0] = s2;
        }
        __syncthreads();
        cls += wsf[0] + (float)k * __uint_as_float(prefix);  // residual ties
    }

    if (tid == 0) {
        g_batch_cls[b] = cls;
        __threadfence();
        int v = atomicAdd(&g_done, 1);
        sh_last = (v == B - 1) ? 1 : 0;
    }
    __syncthreads();

    // ---- last-finishing block: finalize ----
    if (sh_last) {
        float box = 0.0f, ctot = 0.0f; int npos = 0;
        for (int i = tid; i < B; i += NT) {
            box  += *(volatile float*)&g_batch_box[i];
            ctot += *(volatile float*)&g_batch_cls[i];
            npos += *(volatile int*)&g_batch_np[i];
        }
#pragma unroll
        for (int o = 16; o > 0; o >>= 1) {
            box  += __shfl_down_sync(0xffffffffu, box, o);
            ctot += __shfl_down_sync(0xffffffffu, ctot, o);
            npos += __shfl_down_sync(0xffffffffu, npos, o);
        }
        if (lane == 0) { wsf[warp] = box; wsf2[warp] = ctot; wsi[warp] = npos; }
        __syncthreads();
        if (tid == 0) {
            float b2 = 0.f, c2 = 0.f; int n2 = 0;
#pragma unroll
            for (int w2 = 0; w2 < 32; w2++) { b2 += wsf[w2]; c2 += wsf2[w2]; n2 += wsi[w2]; }
            float inv = 1.0f / (float)n2;
            out[0] = b2 * inv;
            out[1] = c2 * inv;
            g_done = 0;                                  // self-reset for replay
        }
    }
}

// =====================================================================
extern "C" void kernel_launch(void* const* d_in, const int* in_sizes, int n_in,
                              void* d_out, int out_size)
{
    const float* priors = (const float*)d_in[0];
    const float* logits = (const float*)d_in[1];
    const float* boxreg = (const float*)d_in[2];
    const float* gtb    = (const float*)d_in[3];
    const int*   gtl    = (const int*)d_in[4];

    const int P = in_sizes[0] / 4;
    const int B = in_sizes[2] / (4 * P);
    const int C = in_sizes[1] / (B * P);
    const int G = in_sizes[4] / B;

    const int nTiles = (P + TILE - 1) / TILE;
    const int nblk   = (P + SM_ROWS - 1) / SM_ROWS;
    const int nMatch = B * nTiles;

    fused_ms<<<nMatch + B * nblk, 256>>>(logits, priors, boxreg, gtb, gtl,
                                         P, C, G, nMatch, nTiles, nblk);

    topk_kernel<<<B, 1024>>>((float*)d_out, logits, priors, boxreg, gtb, gtl,
                             P, C, G, B, nblk);
}

// round 15
// speedup vs baseline: 2.1014x; 2.1014x over previous
#include <cuda_runtime.h>
#include <math.h>
#include <stdint.h>

#define MAXB    64
#define MAXP    8732
#define MAXBP   (MAXB * MAXP)
#define MAXG    16
#define TILE    256
#define SM_ROWS 64

// ---------------- scratch (static device globals; zero-initialized) -------------
__device__ unsigned      g_negkey[MAXBP];
__device__ unsigned char g_mbyte[MAXBP];                 // bit7 = pos, bits0-3 = argmax g
__device__ unsigned long long g_bestkey[MAXB * MAXG];    // zero-init; reset by K2
__device__ float g_batch_cls[MAXB];
__device__ float g_batch_box[MAXB];
__device__ int   g_batch_np[MAXB];
__device__ int   g_done;

__device__ __forceinline__ unsigned smem_u32(const void* p) {
    unsigned a;
    asm("{ .reg .u64 t; cvta.to.shared.u64 t, %1; cvt.u32.u64 %0, t; }"
        : "=r"(a) : "l"(p));
    return a;
}

// =====================================================================
// K1: heterogeneous kernel, match blocks interleaved 1-in-4 with
// softmax blocks.  Softmax tile staged via TMA bulk copy (UBLKCP).
// Match IoU uses fast approximate division: consumers are comparisons
// whose gaps are ~1e-2..1e-3 rel, vastly above fdividef's ~2-ulp error.
// =====================================================================
__global__ __launch_bounds__(256) void fused_ms(
    const float* __restrict__ logits,
    const float* __restrict__ priors,
    const float* __restrict__ gt_boxes,
    int P, int C, int G, int nMatch, int nTiles, int nblk)
{
    __shared__ float4 sbuf4[SM_ROWS * 81 / 4];    // softmax stage / match iou tile
    __shared__ float gx0[MAXG], gy0[MAXG], gx1[MAXG], gy1[MAXG], ga[MAXG];
    __shared__ unsigned long long mbar;

    const int tid = threadIdx.x;
    const int bid = blockIdx.x;
    const bool isMatch = ((bid & 3) == 0) && ((bid >> 2) < nMatch);

    if (isMatch) {
        // ---------------- match role: 256 priors per block ----------------
        const int mi = bid >> 2;
        const int b = mi / nTiles;
        const int t = mi % nTiles;
        unsigned* siou = (unsigned*)sbuf4;        // [16][TILE] iou bits

        if (tid < G) {
            float4 gv = __ldg((const float4*)gt_boxes + b * G + tid);
            gx0[tid] = gv.x; gy0[tid] = gv.y; gx1[tid] = gv.z; gy1[tid] = gv.w;
            ga[tid]  = (gv.z - gv.x) * (gv.w - gv.y);
        }
        __syncthreads();

        const int p0 = t * TILE;
        const int p  = p0 + tid;

        if (p < P) {
            float4 pv = __ldg((const float4*)priors + p);
            float px0 = pv.x - 0.5f * pv.z, py0 = pv.y - 0.5f * pv.w;
            float px1 = pv.x + 0.5f * pv.z, py1 = pv.y + 0.5f * pv.w;
            float parea = (px1 - px0) * (py1 - py0);

            float mval = -1.0f; int mg = 0;
#pragma unroll
            for (int g = 0; g < MAXG; g++) {
                if (g >= G) break;
                float ix0 = fmaxf(gx0[g], px0), iy0 = fmaxf(gy0[g], py0);
                float ix1 = fminf(gx1[g], px1), iy1 = fminf(gy1[g], py1);
                float iw = fmaxf(ix1 - ix0, 0.0f), ih = fmaxf(iy1 - iy0, 0.0f);
                float inter = iw * ih;
                float iou = __fdividef(inter, ga[g] + parea - inter); // approx div
                if (iou > mval) { mval = iou; mg = g; }      // first-g tie-break
                siou[g * TILE + tid] = __float_as_uint(iou); // iou>=0 => ordered bits
            }
            g_mbyte[b * P + p] =
                (unsigned char)(mg | ((mval >= 0.5f) ? 0x80 : 0));
        } else {
#pragma unroll
            for (int g = 0; g < MAXG; g++) {
                if (g >= G) break;
                siou[g * TILE + tid] = 0u;
            }
        }
        __syncthreads();

        const int warp = tid >> 5, lane = tid & 31;
#pragma unroll
        for (int gg = warp; gg < MAXG; gg += 8) {
            if (gg >= G) break;
            unsigned long long best = 0ull;
#pragma unroll
            for (int i = 0; i < TILE / 32; i++) {
                const int c = lane + 32 * i;
                unsigned bits = siou[gg * TILE + c];
                unsigned long long key =
                    ((unsigned long long)bits << 32) |
                    (unsigned long long)(0xFFFFFFFFu - (unsigned)(p0 + c));
                if (key > best) best = key;                  // lower p wins ties
            }
#pragma unroll
            for (int o = 16; o > 0; o >>= 1) {
                unsigned long long other = __shfl_down_sync(0xffffffffu, best, o);
                if (other > best) best = other;
            }
            if (lane == 0) atomicMax(&g_bestkey[b * MAXG + gg], best);
        }
    } else {
        // ---------------- softmax role: 64 rows per block, TMA staged ------
        const int nm_before = min((bid + 3) >> 2, nMatch);
        const int r  = bid - nm_before;
        const int b  = r / nblk;
        const int bx = r % nblk;
        const int r0 = bx * SM_ROWS;
        const int R  = min(SM_ROWS, P - r0);

        const float* base = logits + ((size_t)b * P + r0) * C;
        const unsigned nbytes = (unsigned)(R * C * 4);   // R % 4 == 0 -> 16B multiple

        const unsigned mb_addr = smem_u32(&mbar);
        const unsigned dst     = smem_u32(sbuf4);
        if (tid == 0) {
            asm volatile("mbarrier.init.shared.b64 [%0], %1;"
                         :: "r"(mb_addr), "r"(1) : "memory");
        }
        __syncthreads();
        if (tid == 0) {
            asm volatile("mbarrier.arrive.expect_tx.shared.b64 _, [%0], %1;"
                         :: "r"(mb_addr), "r"(nbytes) : "memory");
            asm volatile(
                "cp.async.bulk.shared::cta.global.mbarrier::complete_tx::bytes "
                "[%0], [%1], %2, [%3];"
                :: "r"(dst), "l"(base), "r"(nbytes), "r"(mb_addr) : "memory");
        }
        // wait for TMA completion (phase 0)
        {
            unsigned done;
            do {
                asm volatile(
                    "{\n\t.reg .pred p;\n\t"
                    "mbarrier.try_wait.parity.shared.b64 p, [%1], 0;\n\t"
                    "selp.b32 %0, 1, 0, p;\n\t}"
                    : "=r"(done) : "r"(mb_addr) : "memory");
            } while (!done);
        }
        __syncthreads();

        const float* sbuf = (const float*)sbuf4;
        const int warp = tid >> 5, lane = tid & 31;
#pragma unroll
        for (int j = 0; j < SM_ROWS / 8; j++) {
            const int row = warp + j * 8;
            if (row >= R) break;
            const float* rp = sbuf + row * 81;
            float sum = 0.0f;
            if (lane      < C) sum += __expf(rp[lane]);
            if (lane + 32 < C) sum += __expf(rp[lane + 32]);
            if (lane + 64 < C) sum += __expf(rp[lane + 64]);
#pragma unroll
            for (int o = 16; o > 0; o >>= 1)
                sum += __shfl_xor_sync(0xffffffffu, sum, o);
            if (lane == 0) {
                float lse = __logf(sum);
                g_negkey[b * P + r0 + row] =
                    __float_as_uint(fmaxf(lse - rp[0], 0.0f));   // bg_loss >= 0
            }
        }
    }
}

// =====================================================================
// K2: per-batch apply + exact top-k + finalize.  One block per batch,
// 1024 threads.  Batched staging (MLP=3), word-wise positive scan,
// warp-aggregated histogram atomics.
// =====================================================================
__global__ __launch_bounds__(1024) void apply_topk(
    float* __restrict__ out,
    const float* __restrict__ logits,
    const float* __restrict__ priors,
    const float* __restrict__ box_reg,
    const float* __restrict__ gt_boxes,
    const int*   __restrict__ gt_labels,
    int P, int C, int G, int B)
{
    const int b = blockIdx.x;
    const int tid = threadIdx.x;
    const int NT = 1024;
    const int lane = tid & 31, warp = tid >> 5;

    __shared__ unsigned sk[MAXP];                 // 34.9 KB keys
    __shared__ int   hist[4096];                  // aliased as match bytes
    __shared__ int   suf[256];
    __shared__ float wsf[32], wsf2[32];
    __shared__ int   wsi[32];
    __shared__ float gx0[MAXG], gy0[MAXG], gx1[MAXG], gy1[MAXG];
    __shared__ int   glab[MAXG], bp[MAXG];
    __shared__ int   f_bucket, f_above, sh_k, sh_last;
    __shared__ float sh_ce;
    unsigned char* smb = (unsigned char*)hist;    // apply phase only

    // stage keys + match bytes, batched loads (MLP=3 each)
    {
        const int nv = P >> 2;                    // P % 4 == 0
        const uint4* nk4 = (const uint4*)(g_negkey + b * P);
        const unsigned* mb4 = (const unsigned*)(g_mbyte + b * P);
        uint4 kv[3]; unsigned mv[3]; bool gd[3];
#pragma unroll
        for (int kk = 0; kk < 3; kk++) {
            const int i = tid + kk * NT;
            gd[kk] = i < nv;
            if (gd[kk]) { kv[kk] = __ldg(&nk4[i]); mv[kk] = __ldg(&mb4[i]); }
        }
#pragma unroll
        for (int kk = 0; kk < 3; kk++) {
            const int i = tid + kk * NT;
            if (gd[kk]) {
                sk[i * 4 + 0] = kv[kk].x; sk[i * 4 + 1] = kv[kk].y;
                sk[i * 4 + 2] = kv[kk].z; sk[i * 4 + 3] = kv[kk].w;
                ((unsigned*)smb)[i] = mv[kk];
            }
        }
        for (int i = tid + 3 * NT; i < nv; i += NT) {   // safety tail
            uint4 v = __ldg(&nk4[i]);
            sk[i * 4 + 0] = v.x; sk[i * 4 + 1] = v.y;
            sk[i * 4 + 2] = v.z; sk[i * 4 + 3] = v.w;
            ((unsigned*)smb)[i] = __ldg(&mb4[i]);
        }
    }
    if (tid < G) {
        float4 gv = __ldg((const float4*)gt_boxes + b * G + tid);
        gx0[tid] = gv.x; gy0[tid] = gv.y; gx1[tid] = gv.z; gy1[tid] = gv.w;
        glab[tid] = gt_labels[b * G + tid];
        unsigned long long k = g_bestkey[b * MAXG + tid];
        bp[tid] = (int)(0xFFFFFFFFu - (unsigned)(k & 0xFFFFFFFFull));
        g_bestkey[b * MAXG + tid] = 0ull;         // reset for next replay
    }
    __syncthreads();

    // inject best-prior overrides (ascending g: last-GT-wins, matches .set)
    if (tid == 0) {
        for (int g = 0; g < G; g++)
            smb[bp[g]] = (unsigned char)(0x80 | g);
    }
    __syncthreads();

    // ---- apply: word-wise scan, positives -> CE + box smooth-L1 ----
    float ce = 0.0f, bxs = 0.0f;
    int np = 0;
    {
        const int nwords = P >> 2;
        for (int i = tid; i < nwords; i += NT) {
            unsigned w4 = ((const unsigned*)smb)[i];
            if (w4 & 0x80808080u) {
#pragma unroll
                for (int j = 0; j < 4; j++) {
                    if ((w4 >> (8 * j + 7)) & 1u) {
                        const int p = i * 4 + j;
                        const int mg = (w4 >> (8 * j)) & 15;
                        np++;
                        float bg = __uint_as_float(sk[p]);
                        sk[p] = 0u;
                        const float* rowp = logits + ((size_t)(b * P + p)) * C;
                        float x0 = __ldg(rowp);
                        float xl = __ldg(rowp + glab[mg]);
                        ce += bg + x0 - xl;                // = lse - x[lab]

                        float4 pv = __ldg((const float4*)priors + p);
                        float bx0 = gx0[mg], by0 = gy0[mg];
                        float bx1 = gx1[mg], by1 = gy1[mg];
                        float t0 = ((bx0 + bx1) * 0.5f - pv.x) / (0.1f * pv.z);
                        float t1 = ((by0 + by1) * 0.5f - pv.y) / (0.1f * pv.w);
                        float t2 = __logf((bx1 - bx0) / pv.z) / 0.2f;
                        float t3 = __logf((by1 - by0) / pv.w) / 0.2f;
                        float4 br = __ldg((const float4*)box_reg + (b * P + p));
                        float d0 = fabsf(br.x - t0), d1 = fabsf(br.y - t1);
                        float d2 = fabsf(br.z - t2), d3 = fabsf(br.w - t3);
                        bxs += (d0 < 1.0f) ? 0.5f * d0 * d0 : d0 - 0.5f;
                        bxs += (d1 < 1.0f) ? 0.5f * d1 * d1 : d1 - 0.5f;
                        bxs += (d2 < 1.0f) ? 0.5f * d2 * d2 : d2 - 0.5f;
                        bxs += (d3 < 1.0f) ? 0.5f * d3 * d3 : d3 - 0.5f;
                    }
                }
            }
        }
    }
    // shuffle block reduction (ce, box, np)
#pragma unroll
    for (int o = 16; o > 0; o >>= 1) {
        ce  += __shfl_down_sync(0xffffffffu, ce, o);
        bxs += __shfl_down_sync(0xffffffffu, bxs, o);
        np  += __shfl_down_sync(0xffffffffu, np, o);
    }
    if (lane == 0) { wsf[warp] = ce; wsf2[warp] = bxs; wsi[warp] = np; }
    __syncthreads();
    if (warp == 0) {
        float c2 = wsf[lane], b2 = wsf2[lane];
        int n2 = wsi[lane];
#pragma unroll
        for (int o = 16; o > 0; o >>= 1) {
            c2 += __shfl_down_sync(0xffffffffu, c2, o);
            b2 += __shfl_down_sync(0xffffffffu, b2, o);
            n2 += __shfl_down_sync(0xffffffffu, n2, o);
        }
        if (lane == 0) {
            int k = n2 * 3; if (k > P) k = P;
            sh_k = k; sh_ce = c2;
            g_batch_box[b] = b2;
            g_batch_np[b]  = n2;
        }
    }
    __syncthreads();
    int k = sh_k;

    // ---- exact top-k sum: 3-pass histogram select, warp-aggregated ----
    float cls = sh_ce;
    if (k > 0) {
        unsigned prefix = 0;
        const int shifts[3] = {20, 8, 0};
        const int bitsA[3]  = {12, 12, 8};
        const int iters = (P + NT - 1) / NT;
#pragma unroll
        for (int ps = 0; ps < 3; ps++) {
            const int shift = shifts[ps];
            const int nbits = bitsA[ps];
            const int nb = 1 << nbits;
            const unsigned himask = (unsigned)(~((1ull << (shift + nbits)) - 1ull));

            for (int i = tid; i < nb; i += NT) hist[i] = 0;
            __syncthreads();

            for (int it = 0; it < iters; it++) {
                const int p = tid + it * NT;
                unsigned key = (p < P) ? sk[p] : 0u;
                const bool act = (p < P) && ((key & himask) == prefix);
                unsigned bkt = act ? ((key >> shift) & (nb - 1)) : 0xFFFFFFFFu;
                unsigned mm = __match_any_sync(0xffffffffu, bkt);
                if (act && ((int)(__ffs(mm) - 1) == lane))
                    atomicAdd(&hist[bkt], __popc(mm));
            }
            __syncthreads();

            // suffix scan over 256 chunk sums (warp shuffles)
            const int cw = nb >> 8;
            int cs = 0;
            if (tid < 256)
                for (int i = 0; i < cw; i++) cs += hist[tid * cw + i];
            int v = cs;
#pragma unroll
            for (int o = 1; o < 32; o <<= 1) {
                int u = __shfl_down_sync(0xffffffffu, v, o);
                if (lane + o < 32) v += u;
            }
            if (tid < 256 && lane == 0) wsi[warp] = v;   // warp totals (warps 0-7)
            __syncthreads();
            if (tid < 256) {
                int off = 0;
                for (int w2 = warp + 1; w2 < 8; w2++) off += wsi[w2];
                suf[tid] = v + off;                      // inclusive suffix
            }
            __syncthreads();
            if (tid < 256) {
                int running = suf[tid] - cs;             // strictly above my chunk
                for (int i = cw - 1; i >= 0; i--) {
                    int c = hist[tid * cw + i];
                    if (c > 0 && running < k && running + c >= k) {
                        f_bucket = tid * cw + i;         // unique writer
                        f_above  = running;
                    }
                    running += c;
                }
            }
            __syncthreads();
            prefix |= ((unsigned)f_bucket) << shift;
            k -= f_above;
            __syncthreads();
        }

        float ss = 0.0f;
        for (int p = tid; p < P; p += NT) {
            unsigned key = sk[p];
            if (key > prefix) ss += __uint_as_float(key);
        }
#pragma unroll
        for (int o = 16; o > 0; o >>= 1) ss += __shfl_down_sync(0xffffffffu, ss, o);
        if (lane == 0) wsf[warp] = ss;
        __syncthreads();
        if (warp == 0) {
            float s2 = wsf[lane];
#pragma unroll
            for (int o = 16; o > 0; o >>= 1) s2 += __shfl_down_sync(0xffffffffu, s2, o);
            if (lane == 0) wsf[0] = s2;
        }
        __syncthreads();
        cls += wsf[0] + (float)k * __uint_as_float(prefix);  // residual ties
    }

    if (tid == 0) {
        g_batch_cls[b] = cls;
        __threadfence();
        int v = atomicAdd(&g_done, 1);
        sh_last = (v == B - 1) ? 1 : 0;
    }
    __syncthreads();

    // ---- last-finishing block: finalize ----
    if (sh_last) {
        float box = 0.0f, ctot = 0.0f; int npos = 0;
        for (int i = tid; i < B; i += NT) {
            box  += *(volatile float*)&g_batch_box[i];
            ctot += *(volatile float*)&g_batch_cls[i];
            npos += *(volatile int*)&g_batch_np[i];
        }
#pragma unroll
        for (int o = 16; o > 0; o >>= 1) {
            box  += __shfl_down_sync(0xffffffffu, box, o);
            ctot += __shfl_down_sync(0xffffffffu, ctot, o);
            npos += __shfl_down_sync(0xffffffffu, npos, o);
        }
        if (lane == 0) { wsf[warp] = box; wsf2[warp] = ctot; wsi[warp] = npos; }
        __syncthreads();
        if (warp == 0) {
            float b2 = wsf[lane], c2 = wsf2[lane];
            int n2 = wsi[lane];
#pragma unroll
            for (int o = 16; o > 0; o >>= 1) {
                b2 += __shfl_down_sync(0xffffffffu, b2, o);
                c2 += __shfl_down_sync(0xffffffffu, c2, o);
                n2 += __shfl_down_sync(0xffffffffu, n2, o);
            }
            if (lane == 0) {
                float inv = 1.0f / (float)n2;
                out[0] = b2 * inv;
                out[1] = c2 * inv;
                g_done = 0;                              // self-reset for replay
            }
        }
    }
}

// =====================================================================
extern "C" void kernel_launch(void* const* d_in, const int* in_sizes, int n_in,
                              void* d_out, int out_size)
{
    const float* priors = (const float*)d_in[0];
    const float* logits = (const float*)d_in[1];
    const float* boxreg = (const float*)d_in[2];
    const float* gtb    = (const float*)d_in[3];
    const int*   gtl    = (const int*)d_in[4];

    const int P = in_sizes[0] / 4;
    const int B = in_sizes[2] / (4 * P);
    const int C = in_sizes[1] / (B * P);
    const int G = in_sizes[4] / B;

    const int nTiles = (P + TILE - 1) / TILE;
    const int nblk   = (P + SM_ROWS - 1) / SM_ROWS;
    const int nMatch = B * nTiles;

    fused_ms<<<nMatch + B * nblk, 256>>>(logits, priors, gtb,
                                         P, C, G, nMatch, nTiles, nblk);

    apply_topk<<<B, 1024>>>((float*)d_out, logits, priors, boxreg, gtb, gtl,
                            P, C, G, B);
}

// round 16
// speedup vs baseline: 2.1853x; 1.0399x over previous
#include <cuda_runtime.h>
#include <math.h>
#include <stdint.h>

#define MAXB    64
#define MAXP    8732
#define MAXBP   (MAXB * MAXP)
#define MAXG    16
#define TILE    256
#define SM_ROWS 64
#define NQ      9          // ceil(MAXP / 1024)

// ---------------- scratch (static device globals; zero-initialized) -------------
__device__ unsigned      g_negkey[MAXBP];
__device__ unsigned char g_mbyte[MAXBP];                 // bit7 = pos, bits0-3 = argmax g
__device__ unsigned long long g_bestkey[MAXB * MAXG];    // zero-init; reset by K2
__device__ float g_batch_cls[MAXB];
__device__ float g_batch_box[MAXB];
__device__ int   g_batch_np[MAXB];
__device__ int   g_done;

__device__ __forceinline__ unsigned smem_u32(const void* p) {
    unsigned a;
    asm("{ .reg .u64 t; cvta.to.shared.u64 t, %1; cvt.u32.u64 %0, t; }"
        : "=r"(a) : "l"(p));
    return a;
}

// =====================================================================
// K1: heterogeneous kernel, match blocks interleaved 1-in-4 with
// softmax blocks.  Softmax tile staged via TMA bulk copy (UBLKCP).
// Match IoU uses fast approximate division (comparison consumers only).
// =====================================================================
__global__ __launch_bounds__(256) void fused_ms(
    const float* __restrict__ logits,
    const float* __restrict__ priors,
    const float* __restrict__ gt_boxes,
    int P, int C, int G, int nMatch, int nTiles, int nblk)
{
    __shared__ float4 sbuf4[SM_ROWS * 81 / 4];    // softmax stage / match iou tile
    __shared__ float gx0[MAXG], gy0[MAXG], gx1[MAXG], gy1[MAXG], ga[MAXG];
    __shared__ unsigned long long mbar;

    const int tid = threadIdx.x;
    const int bid = blockIdx.x;
    const bool isMatch = ((bid & 3) == 0) && ((bid >> 2) < nMatch);

    if (isMatch) {
        const int mi = bid >> 2;
        const int b = mi / nTiles;
        const int t = mi % nTiles;
        unsigned* siou = (unsigned*)sbuf4;        // [16][TILE] iou bits

        if (tid < G) {
            float4 gv = __ldg((const float4*)gt_boxes + b * G + tid);
            gx0[tid] = gv.x; gy0[tid] = gv.y; gx1[tid] = gv.z; gy1[tid] = gv.w;
            ga[tid]  = (gv.z - gv.x) * (gv.w - gv.y);
        }
        __syncthreads();

        const int p0 = t * TILE;
        const int p  = p0 + tid;

        if (p < P) {
            float4 pv = __ldg((const float4*)priors + p);
            float px0 = pv.x - 0.5f * pv.z, py0 = pv.y - 0.5f * pv.w;
            float px1 = pv.x + 0.5f * pv.z, py1 = pv.y + 0.5f * pv.w;
            float parea = (px1 - px0) * (py1 - py0);

            float mval = -1.0f; int mg = 0;
#pragma unroll
            for (int g = 0; g < MAXG; g++) {
                if (g >= G) break;
                float ix0 = fmaxf(gx0[g], px0), iy0 = fmaxf(gy0[g], py0);
                float ix1 = fminf(gx1[g], px1), iy1 = fminf(gy1[g], py1);
                float iw = fmaxf(ix1 - ix0, 0.0f), ih = fmaxf(iy1 - iy0, 0.0f);
                float inter = iw * ih;
                float iou = __fdividef(inter, ga[g] + parea - inter);
                if (iou > mval) { mval = iou; mg = g; }      // first-g tie-break
                siou[g * TILE + tid] = __float_as_uint(iou); // iou>=0 => ordered bits
            }
            g_mbyte[b * P + p] =
                (unsigned char)(mg | ((mval >= 0.5f) ? 0x80 : 0));
        } else {
#pragma unroll
            for (int g = 0; g < MAXG; g++) {
                if (g >= G) break;
                siou[g * TILE + tid] = 0u;
            }
        }
        __syncthreads();

        const int warp = tid >> 5, lane = tid & 31;
#pragma unroll
        for (int gg = warp; gg < MAXG; gg += 8) {
            if (gg >= G) break;
            unsigned long long best = 0ull;
#pragma unroll
            for (int i = 0; i < TILE / 32; i++) {
                const int c = lane + 32 * i;
                unsigned bits = siou[gg * TILE + c];
                unsigned long long key =
                    ((unsigned long long)bits << 32) |
                    (unsigned long long)(0xFFFFFFFFu - (unsigned)(p0 + c));
                if (key > best) best = key;                  // lower p wins ties
            }
#pragma unroll
            for (int o = 16; o > 0; o >>= 1) {
                unsigned long long other = __shfl_down_sync(0xffffffffu, best, o);
                if (other > best) best = other;
            }
            if (lane == 0) atomicMax(&g_bestkey[b * MAXG + gg], best);
        }
    } else {
        const int nm_before = min((bid + 3) >> 2, nMatch);
        const int r  = bid - nm_before;
        const int b  = r / nblk;
        const int bx = r % nblk;
        const int r0 = bx * SM_ROWS;
        const int R  = min(SM_ROWS, P - r0);

        const float* base = logits + ((size_t)b * P + r0) * C;
        const unsigned nbytes = (unsigned)(R * C * 4);   // 16B multiple

        const unsigned mb_addr = smem_u32(&mbar);
        const unsigned dst     = smem_u32(sbuf4);
        if (tid == 0) {
            asm volatile("mbarrier.init.shared.b64 [%0], %1;"
                         :: "r"(mb_addr), "r"(1) : "memory");
        }
        __syncthreads();
        if (tid == 0) {
            asm volatile("mbarrier.arrive.expect_tx.shared.b64 _, [%0], %1;"
                         :: "r"(mb_addr), "r"(nbytes) : "memory");
            asm volatile(
                "cp.async.bulk.shared::cta.global.mbarrier::complete_tx::bytes "
                "[%0], [%1], %2, [%3];"
                :: "r"(dst), "l"(base), "r"(nbytes), "r"(mb_addr) : "memory");
        }
        {
            unsigned done;
            do {
                asm volatile(
                    "{\n\t.reg .pred p;\n\t"
                    "mbarrier.try_wait.parity.shared.b64 p, [%1], 0;\n\t"
                    "selp.b32 %0, 1, 0, p;\n\t}"
                    : "=r"(done) : "r"(mb_addr) : "memory");
            } while (!done);
        }
        __syncthreads();

        const float* sbuf = (const float*)sbuf4;
        const int warp = tid >> 5, lane = tid & 31;
#pragma unroll
        for (int j = 0; j < SM_ROWS / 8; j++) {
            const int row = warp + j * 8;
            if (row >= R) break;
            const float* rp = sbuf + row * 81;
            float sum = 0.0f;
            if (lane      < C) sum += __expf(rp[lane]);
            if (lane + 32 < C) sum += __expf(rp[lane + 32]);
            if (lane + 64 < C) sum += __expf(rp[lane + 64]);
#pragma unroll
            for (int o = 16; o > 0; o >>= 1)
                sum += __shfl_xor_sync(0xffffffffu, sum, o);
            if (lane == 0) {
                float lse = __logf(sum);
                g_negkey[b * P + r0 + row] =
                    __float_as_uint(fmaxf(lse - rp[0], 0.0f));   // bg_loss >= 0
            }
        }
    }
}

// =====================================================================
// K2: per-batch apply + exact top-k + finalize.  One block per batch,
// 1024 threads.  Keys live in registers (9/thread); 2 radix passes +
// warp candidate resolution replace the 3rd pass; no smem key staging.
// =====================================================================
__global__ __launch_bounds__(1024) void apply_topk(
    float* __restrict__ out,
    const float* __restrict__ logits,
    const float* __restrict__ priors,
    const float* __restrict__ box_reg,
    const float* __restrict__ gt_boxes,
    const int*   __restrict__ gt_labels,
    int P, int C, int G, int B)
{
    const int b = blockIdx.x;
    const int tid = threadIdx.x;
    const int NT = 1024;
    const int lane = tid & 31, warp = tid >> 5;

    __shared__ int   hist[4096];
    __shared__ int   suf[256];
    __shared__ float wsf[32], wsf2[32];
    __shared__ int   wsi[32];
    __shared__ float gx0[MAXG], gy0[MAXG], gx1[MAXG], gy1[MAXG];
    __shared__ int   glab[MAXG], bp[MAXG];
    __shared__ unsigned cand[32];
    __shared__ int   cand_cnt;
    __shared__ int   f_bucket, f_above, sh_k, sh_last, sh_kres;
    __shared__ float sh_ce;
    __shared__ unsigned sh_thr;

    if (tid < G) {
        float4 gv = __ldg((const float4*)gt_boxes + b * G + tid);
        gx0[tid] = gv.x; gy0[tid] = gv.y; gx1[tid] = gv.z; gy1[tid] = gv.w;
        glab[tid] = gt_labels[b * G + tid];
        unsigned long long k = g_bestkey[b * MAXG + tid];
        bp[tid] = (int)(0xFFFFFFFFu - (unsigned)(k & 0xFFFFFFFFull));
        g_bestkey[b * MAXG + tid] = 0ull;         // reset for next replay
    }
    if (tid == 0) cand_cnt = 0;
    __syncthreads();

    // ---- load keys + apply (overrides via direct bp compare) ----
    unsigned key[NQ];
    float ce = 0.0f, bxs = 0.0f;
    int np = 0;
#pragma unroll
    for (int q = 0; q < NQ; q++) {
        const int p = tid + q * NT;
        const bool valid = (q < NQ - 1) || (p < P);
        key[q] = valid ? __ldg(&g_negkey[b * P + p]) : 0u;
        unsigned char mb = valid ? __ldg(&g_mbyte[b * P + p]) : 0;
        int mg  = mb & 15;
        int pos = mb >> 7;
        if (valid) {
#pragma unroll
            for (int g = 0; g < MAXG; g++) {      // ascending: last-GT-wins (.set)
                if (g >= G) break;
                if (bp[g] == p) { mg = g; pos = 1; }
            }
        }
        if (pos) {
            np++;
            float bg = __uint_as_float(key[q]);
            key[q] = 0u;                          // exclude from hard-neg pool
            const float* rowp = logits + ((size_t)(b * P + p)) * C;
            float x0 = __ldg(rowp);
            float xl = __ldg(rowp + glab[mg]);
            ce += bg + x0 - xl;                   // = lse - x[lab]

            float4 pv = __ldg((const float4*)priors + p);
            float bx0 = gx0[mg], by0 = gy0[mg], bx1 = gx1[mg], by1 = gy1[mg];
            float t0 = ((bx0 + bx1) * 0.5f - pv.x) / (0.1f * pv.z);
            float t1 = ((by0 + by1) * 0.5f - pv.y) / (0.1f * pv.w);
            float t2 = __logf((bx1 - bx0) / pv.z) / 0.2f;
            float t3 = __logf((by1 - by0) / pv.w) / 0.2f;
            float4 br = __ldg((const float4*)box_reg + (b * P + p));
            float d0 = fabsf(br.x - t0), d1 = fabsf(br.y - t1);
            float d2 = fabsf(br.z - t2), d3 = fabsf(br.w - t3);
            bxs += (d0 < 1.0f) ? 0.5f * d0 * d0 : d0 - 0.5f;
            bxs += (d1 < 1.0f) ? 0.5f * d1 * d1 : d1 - 0.5f;
            bxs += (d2 < 1.0f) ? 0.5f * d2 * d2 : d2 - 0.5f;
            bxs += (d3 < 1.0f) ? 0.5f * d3 * d3 : d3 - 0.5f;
        }
    }
    // block reduction (ce, box, np)
#pragma unroll
    for (int o = 16; o > 0; o >>= 1) {
        ce  += __shfl_down_sync(0xffffffffu, ce, o);
        bxs += __shfl_down_sync(0xffffffffu, bxs, o);
        np  += __shfl_down_sync(0xffffffffu, np, o);
    }
    if (lane == 0) { wsf[warp] = ce; wsf2[warp] = bxs; wsi[warp] = np; }
    __syncthreads();
    if (warp == 0) {
        float c2 = wsf[lane], b2 = wsf2[lane];
        int n2 = wsi[lane];
#pragma unroll
        for (int o = 16; o > 0; o >>= 1) {
            c2 += __shfl_down_sync(0xffffffffu, c2, o);
            b2 += __shfl_down_sync(0xffffffffu, b2, o);
            n2 += __shfl_down_sync(0xffffffffu, n2, o);
        }
        if (lane == 0) {
            int k = n2 * 3; if (k > P) k = P;
            sh_k = k; sh_ce = c2;
            g_batch_box[b] = b2;
            g_batch_np[b]  = n2;
        }
    }
    __syncthreads();
    int k = sh_k;

    float cls = sh_ce;
    if (k > 0) {
        // =================== pass 1: bits [31:20] =====================
        for (int i = tid; i < 4096; i += NT) hist[i] = 0;
        __syncthreads();
#pragma unroll
        for (int q = 0; q < NQ; q++) {
            const bool valid = (q < NQ - 1) || (tid + q * NT < P);
            unsigned bkt = valid ? (key[q] >> 20) : 0xFFFFFFFFu;
            unsigned mm = __match_any_sync(0xffffffffu, bkt);
            if (valid && ((int)(__ffs(mm) - 1) == lane))
                atomicAdd(&hist[bkt], __popc(mm));
        }
        __syncthreads();
        {   // select bucket (cw = 16)
            const int cw = 16;
            int cs = 0;
            if (tid < 256)
                for (int i = 0; i < cw; i++) cs += hist[tid * cw + i];
            int v = cs;
#pragma unroll
            for (int o = 1; o < 32; o <<= 1) {
                int u = __shfl_down_sync(0xffffffffu, v, o);
                if (lane + o < 32) v += u;
            }
            if (tid < 256 && lane == 0) wsi[warp] = v;
            __syncthreads();
            if (tid < 256) {
                int off = 0;
                for (int w2 = warp + 1; w2 < 8; w2++) off += wsi[w2];
                suf[tid] = v + off;
            }
            __syncthreads();
            if (tid < 256) {
                int running = suf[tid] - cs;
                for (int i = cw - 1; i >= 0; i--) {
                    int c = hist[tid * cw + i];
                    if (c > 0 && running < k && running + c >= k) {
                        f_bucket = tid * cw + i;
                        f_above  = running;
                    }
                    running += c;
                }
            }
            __syncthreads();
        }
        const unsigned bkt1 = (unsigned)f_bucket;
        k -= f_above;
        __syncthreads();

        // =================== pass 2: bits [19:8] ======================
        for (int i = tid; i < 4096; i += NT) hist[i] = 0;
        __syncthreads();
#pragma unroll
        for (int q = 0; q < NQ; q++) {
            const bool valid = (q < NQ - 1) || (tid + q * NT < P);
            const bool act = valid && ((key[q] >> 20) == bkt1);
            unsigned bkt = act ? ((key[q] >> 8) & 0xFFF) : 0xFFFFFFFFu;
            unsigned mm = __match_any_sync(0xffffffffu, bkt);
            if (act && ((int)(__ffs(mm) - 1) == lane))
                atomicAdd(&hist[bkt], __popc(mm));
        }
        __syncthreads();
        {
            const int cw = 16;
            int cs = 0;
            if (tid < 256)
                for (int i = 0; i < cw; i++) cs += hist[tid * cw + i];
            int v = cs;
#pragma unroll
            for (int o = 1; o < 32; o <<= 1) {
                int u = __shfl_down_sync(0xffffffffu, v, o);
                if (lane + o < 32) v += u;
            }
            if (tid < 256 && lane == 0) wsi[warp] = v;
            __syncthreads();
            if (tid < 256) {
                int off = 0;
                for (int w2 = warp + 1; w2 < 8; w2++) off += wsi[w2];
                suf[tid] = v + off;
            }
            __syncthreads();
            if (tid < 256) {
                int running = suf[tid] - cs;
                for (int i = cw - 1; i >= 0; i--) {
                    int c = hist[tid * cw + i];
                    if (c > 0 && running < k && running + c >= k) {
                        f_bucket = tid * cw + i;
                        f_above  = running;
                    }
                    running += c;
                }
            }
            __syncthreads();
        }
        const unsigned prefix24 = (bkt1 << 12) | (unsigned)f_bucket;
        k -= f_above;                                   // rank within 24-bit bucket
        __syncthreads();

        // ============ candidate gather (keys sharing 24-bit prefix) ===
#pragma unroll
        for (int q = 0; q < NQ; q++) {
            const bool valid = (q < NQ - 1) || (tid + q * NT < P);
            if (valid && (key[q] >> 8) == prefix24) {
                int idx = atomicAdd(&cand_cnt, 1);
                if (idx < 32) cand[idx] = key[q];
            }
        }
        __syncthreads();

        if (cand_cnt <= 32) {
            // warp 0: rank-resolve exact threshold + tie count
            if (warp == 0) {
                const int m = cand_cnt;
                unsigned ci = (lane < m) ? cand[lane] : 0u;
                int gt = 0, eq = 0;
#pragma unroll
                for (int j = 0; j < 32; j++) {
                    unsigned cj = __shfl_sync(0xffffffffu, ci, j);
                    if (lane < m && j < m) {
                        gt += (cj > ci);
                        eq += (cj == ci);
                    }
                }
                if (lane < m && gt < k && gt + eq >= k) {
                    sh_thr  = ci;                        // exact k-th key value
                    sh_kres = k - gt;                    // ties to include
                }
            }
            __syncthreads();
        } else {
            // fallback: generic 8-bit pass (rare; correctness only)
            for (int i = tid; i < 256; i += NT) hist[i] = 0;
            __syncthreads();
#pragma unroll
            for (int q = 0; q < NQ; q++) {
                const bool valid = (q < NQ - 1) || (tid + q * NT < P);
                const bool act = valid && ((key[q] >> 8) == prefix24);
                unsigned bkt = act ? (key[q] & 0xFF) : 0xFFFFFFFFu;
                unsigned mm = __match_any_sync(0xffffffffu, bkt);
                if (act && ((int)(__ffs(mm) - 1) == lane))
                    atomicAdd(&hist[bkt], __popc(mm));
            }
            __syncthreads();
            {
                const int cw = 1;
                int cs = 0;
                if (tid < 256) cs = hist[tid];
                int v = cs;
#pragma unroll
                for (int o = 1; o < 32; o <<= 1) {
                    int u = __shfl_down_sync(0xffffffffu, v, o);
                    if (lane + o < 32) v += u;
                }
                if (tid < 256 && lane == 0) wsi[warp] = v;
                __syncthreads();
                if (tid < 256) {
                    int off = 0;
                    for (int w2 = warp + 1; w2 < 8; w2++) off += wsi[w2];
                    suf[tid] = v + off;
                }
                __syncthreads();
                if (tid < 256) {
                    int running = suf[tid] - cs;
                    if (cs > 0 && running < k && running + cs >= k) {
                        f_bucket = tid;
                        f_above  = running;
                    }
                }
                __syncthreads();
            }
            if (tid == 0) {
                sh_thr  = (prefix24 << 8) | (unsigned)f_bucket;
                sh_kres = k - f_above;
            }
            __syncthreads();
        }

        // ============ final: sum strictly-greater + residual ties =====
        const unsigned thr = sh_thr;
        float ss = 0.0f;
#pragma unroll
        for (int q = 0; q < NQ; q++) {
            const bool valid = (q < NQ - 1) || (tid + q * NT < P);
            if (valid && key[q] > thr) ss += __uint_as_float(key[q]);
        }
#pragma unroll
        for (int o = 16; o > 0; o >>= 1) ss += __shfl_down_sync(0xffffffffu, ss, o);
        if (lane == 0) wsf[warp] = ss;
        __syncthreads();
        if (warp == 0) {
            float s2 = wsf[lane];
#pragma unroll
            for (int o = 16; o > 0; o >>= 1) s2 += __shfl_down_sync(0xffffffffu, s2, o);
            if (lane == 0) wsf[0] = s2;
        }
        __syncthreads();
        cls += wsf[0] + (float)sh_kres * __uint_as_float(thr);
    }

    if (tid == 0) {
        g_batch_cls[b] = cls;
        __threadfence();
        int v = atomicAdd(&g_done, 1);
        sh_last = (v == B - 1) ? 1 : 0;
    }
    __syncthreads();

    // ---- last-finishing block: finalize ----
    if (sh_last) {
        float box = 0.0f, ctot = 0.0f; int npos = 0;
        for (int i = tid; i < B; i += NT) {
            box  += *(volatile float*)&g_batch_box[i];
            ctot += *(volatile float*)&g_batch_cls[i];
            npos += *(volatile int*)&g_batch_np[i];
        }
#pragma unroll
        for (int o = 16; o > 0; o >>= 1) {
            box  += __shfl_down_sync(0xffffffffu, box, o);
            ctot += __shfl_down_sync(0xffffffffu, ctot, o);
            npos += __shfl_down_sync(0xffffffffu, npos, o);
        }
        if (lane == 0) { wsf[warp] = box; wsf2[warp] = ctot; wsi[warp] = npos; }
        __syncthreads();
        if (warp == 0) {
            float b2 = wsf[lane], c2 = wsf2[lane];
            int n2 = wsi[lane];
#pragma unroll
            for (int o = 16; o > 0; o >>= 1) {
                b2 += __shfl_down_sync(0xffffffffu, b2, o);
                c2 += __shfl_down_sync(0xffffffffu, c2, o);
                n2 += __shfl_down_sync(0xffffffffu, n2, o);
            }
            if (lane == 0) {
                float inv = 1.0f / (float)n2;
                out[0] = b2 * inv;
                out[1] = c2 * inv;
                g_done = 0;                              // self-reset for replay
            }
        }
    }
}

// =====================================================================
extern "C" void kernel_launch(void* const* d_in, const int* in_sizes, int n_in,
                              void* d_out, int out_size)
{
    const float* priors = (const float*)d_in[0];
    const float* logits = (const float*)d_in[1];
    const float* boxreg = (const float*)d_in[2];
    const float* gtb    = (const float*)d_in[3];
    const int*   gtl    = (const int*)d_in[4];

    const int P = in_sizes[0] / 4;
    const int B = in_sizes[2] / (4 * P);
    const int C = in_sizes[1] / (B * P);
    const int G = in_sizes[4] / B;

    const int nTiles = (P + TILE - 1) / TILE;
    const int nblk   = (P + SM_ROWS - 1) / SM_ROWS;
    const int nMatch = B * nTiles;

    fused_ms<<<nMatch + B * nblk, 256>>>(logits, priors, gtb,
                                         P, C, G, nMatch, nTiles, nblk);

    apply_topk<<<B, 1024>>>((float*)d_out, logits, priors, boxreg, gtb, gtl,
                            P, C, G, B);
}

// round 17
// speedup vs baseline: 2.2115x; 1.0120x over previous
#include <cuda_runtime.h>
#include <math.h>
#include <stdint.h>

#define MAXB    64
#define MAXP    8732
#define MAXBP   (MAXB * MAXP)
#define MAXG    16
#define TILE    256
#define SM_ROWS 64
#define NQ      9          // ceil(MAXP / 1024)

// ---------------- scratch (static device globals; zero-initialized) -------------
__device__ unsigned      g_negkey[MAXBP];
__device__ unsigned char g_mbyte[MAXBP];                 // bit7 = pos, bits0-3 = argmax g
__device__ unsigned long long g_bestkey[MAXB * MAXG];    // zero-init; reset by K2
__device__ float g_batch_cls[MAXB];
__device__ float g_batch_box[MAXB];
__device__ int   g_batch_np[MAXB];
__device__ int   g_done;

__device__ __forceinline__ unsigned smem_u32(const void* p) {
    unsigned a;
    asm("{ .reg .u64 t; cvta.to.shared.u64 t, %1; cvt.u32.u64 %0, t; }"
        : "=r"(a) : "l"(p));
    return a;
}

// =====================================================================
// K1: heterogeneous kernel, match blocks interleaved 1-in-4 with
// softmax blocks.  Softmax tile staged via TMA bulk copy (UBLKCP).
// Match IoU uses fast approximate division (comparison consumers only).
// =====================================================================
__global__ __launch_bounds__(256) void fused_ms(
    const float* __restrict__ logits,
    const float* __restrict__ priors,
    const float* __restrict__ gt_boxes,
    int P, int C, int G, int nMatch, int nTiles, int nblk)
{
    __shared__ float4 sbuf4[SM_ROWS * 81 / 4];    // softmax stage / match iou tile
    __shared__ float gx0[MAXG], gy0[MAXG], gx1[MAXG], gy1[MAXG], ga[MAXG];
    __shared__ unsigned long long mbar;

    const int tid = threadIdx.x;
    const int bid = blockIdx.x;
    const bool isMatch = ((bid & 3) == 0) && ((bid >> 2) < nMatch);

    if (isMatch) {
        const int mi = bid >> 2;
        const int b = mi / nTiles;
        const int t = mi % nTiles;
        unsigned* siou = (unsigned*)sbuf4;        // [16][TILE] iou bits

        if (tid < G) {
            float4 gv = __ldg((const float4*)gt_boxes + b * G + tid);
            gx0[tid] = gv.x; gy0[tid] = gv.y; gx1[tid] = gv.z; gy1[tid] = gv.w;
            ga[tid]  = (gv.z - gv.x) * (gv.w - gv.y);
        }
        __syncthreads();

        const int p0 = t * TILE;
        const int p  = p0 + tid;

        if (p < P) {
            float4 pv = __ldg((const float4*)priors + p);
            float px0 = pv.x - 0.5f * pv.z, py0 = pv.y - 0.5f * pv.w;
            float px1 = pv.x + 0.5f * pv.z, py1 = pv.y + 0.5f * pv.w;
            float parea = (px1 - px0) * (py1 - py0);

            float mval = -1.0f; int mg = 0;
#pragma unroll
            for (int g = 0; g < MAXG; g++) {
                if (g >= G) break;
                float ix0 = fmaxf(gx0[g], px0), iy0 = fmaxf(gy0[g], py0);
                float ix1 = fminf(gx1[g], px1), iy1 = fminf(gy1[g], py1);
                float iw = fmaxf(ix1 - ix0, 0.0f), ih = fmaxf(iy1 - iy0, 0.0f);
                float inter = iw * ih;
                float iou = __fdividef(inter, ga[g] + parea - inter);
                if (iou > mval) { mval = iou; mg = g; }      // first-g tie-break
                siou[g * TILE + tid] = __float_as_uint(iou); // iou>=0 => ordered bits
            }
            g_mbyte[b * P + p] =
                (unsigned char)(mg | ((mval >= 0.5f) ? 0x80 : 0));
        } else {
#pragma unroll
            for (int g = 0; g < MAXG; g++) {
                if (g >= G) break;
                siou[g * TILE + tid] = 0u;
            }
        }
        __syncthreads();

        const int warp = tid >> 5, lane = tid & 31;
#pragma unroll
        for (int gg = warp; gg < MAXG; gg += 8) {
            if (gg >= G) break;
            unsigned long long best = 0ull;
#pragma unroll
            for (int i = 0; i < TILE / 32; i++) {
                const int c = lane + 32 * i;
                unsigned bits = siou[gg * TILE + c];
                unsigned long long key =
                    ((unsigned long long)bits << 32) |
                    (unsigned long long)(0xFFFFFFFFu - (unsigned)(p0 + c));
                if (key > best) best = key;                  // lower p wins ties
            }
#pragma unroll
            for (int o = 16; o > 0; o >>= 1) {
                unsigned long long other = __shfl_down_sync(0xffffffffu, best, o);
                if (other > best) best = other;
            }
            if (lane == 0) atomicMax(&g_bestkey[b * MAXG + gg], best);
        }
    } else {
        const int nm_before = min((bid + 3) >> 2, nMatch);
        const int r  = bid - nm_before;
        const int b  = r / nblk;
        const int bx = r % nblk;
        const int r0 = bx * SM_ROWS;
        const int R  = min(SM_ROWS, P - r0);

        const float* base = logits + ((size_t)b * P + r0) * C;
        const unsigned nbytes = (unsigned)(R * C * 4);   // 16B multiple

        const unsigned mb_addr = smem_u32(&mbar);
        const unsigned dst     = smem_u32(sbuf4);
        if (tid == 0) {
            asm volatile("mbarrier.init.shared.b64 [%0], %1;"
                         :: "r"(mb_addr), "r"(1) : "memory");
        }
        __syncthreads();
        if (tid == 0) {
            asm volatile("mbarrier.arrive.expect_tx.shared.b64 _, [%0], %1;"
                         :: "r"(mb_addr), "r"(nbytes) : "memory");
            asm volatile(
                "cp.async.bulk.shared::cta.global.mbarrier::complete_tx::bytes "
                "[%0], [%1], %2, [%3];"
                :: "r"(dst), "l"(base), "r"(nbytes), "r"(mb_addr) : "memory");
        }
        // every thread polls the mbarrier itself -> no barrier needed after
        {
            unsigned done;
            do {
                asm volatile(
                    "{\n\t.reg .pred p;\n\t"
                    "mbarrier.try_wait.parity.shared.b64 p, [%1], 0;\n\t"
                    "selp.b32 %0, 1, 0, p;\n\t}"
                    : "=r"(done) : "r"(mb_addr) : "memory");
            } while (!done);
        }

        const float* sbuf = (const float*)sbuf4;
        const int warp = tid >> 5, lane = tid & 31;
#pragma unroll
        for (int j = 0; j < SM_ROWS / 8; j++) {
            const int row = warp + j * 8;
            if (row >= R) break;
            const float* rp = sbuf + row * 81;
            float sum = 0.0f;
            if (lane      < C) sum += __expf(rp[lane]);
            if (lane + 32 < C) sum += __expf(rp[lane + 32]);
            if (lane + 64 < C) sum += __expf(rp[lane + 64]);
#pragma unroll
            for (int o = 16; o > 0; o >>= 1)
                sum += __shfl_xor_sync(0xffffffffu, sum, o);
            if (lane == 0) {
                float lse = __logf(sum);
                g_negkey[b * P + r0 + row] =
                    __float_as_uint(fmaxf(lse - rp[0], 0.0f));   // bg_loss >= 0
            }
        }
    }
}

// =====================================================================
// K2: per-batch apply + exact top-k + finalize.  One block per batch,
// 1024 threads.  Register-resident keys, shared override byte-array,
// 2 radix passes + warp candidate resolution.
// =====================================================================
__global__ __launch_bounds__(1024) void apply_topk(
    float* __restrict__ out,
    const float* __restrict__ logits,
    const float* __restrict__ priors,
    const float* __restrict__ box_reg,
    const float* __restrict__ gt_boxes,
    const int*   __restrict__ gt_labels,
    int P, int C, int G, int B)
{
    const int b = blockIdx.x;
    const int tid = threadIdx.x;
    const int NT = 1024;
    const int lane = tid & 31, warp = tid >> 5;

    __shared__ int   hist[4096];
    __shared__ unsigned char s_ovr[(MAXP + 7) & ~7];     // override byte per prior
    __shared__ int   suf[256];
    __shared__ float wsf[32], wsf2[32];
    __shared__ int   wsi[32];
    __shared__ float gx0[MAXG], gy0[MAXG], gx1[MAXG], gy1[MAXG];
    __shared__ int   glab[MAXG], bp[MAXG];
    __shared__ unsigned cand[32];
    __shared__ int   cand_cnt;
    __shared__ int   f_bucket, f_above, sh_k, sh_last, sh_kres;
    __shared__ float sh_ce;
    __shared__ unsigned sh_thr;

    // zero override array (word stores)
    {
        unsigned* ow = (unsigned*)s_ovr;
        const int nw = ((MAXP + 7) & ~7) >> 2;
        for (int i = tid; i < nw; i += NT) ow[i] = 0u;
    }
    if (tid < G) {
        float4 gv = __ldg((const float4*)gt_boxes + b * G + tid);
        gx0[tid] = gv.x; gy0[tid] = gv.y; gx1[tid] = gv.z; gy1[tid] = gv.w;
        glab[tid] = gt_labels[b * G + tid];
        unsigned long long k = g_bestkey[b * MAXG + tid];
        bp[tid] = (int)(0xFFFFFFFFu - (unsigned)(k & 0xFFFFFFFFull));
        g_bestkey[b * MAXG + tid] = 0ull;         // reset for next replay
    }
    if (tid == 0) cand_cnt = 0;
    __syncthreads();
    // serial ascending-g writes: exact last-GT-wins (matches .set)
    if (tid == 0) {
        for (int g = 0; g < G; g++)
            s_ovr[bp[g]] = (unsigned char)(0x80 | g);
    }
    __syncthreads();

    // ---- load keys + apply (override via 1 LDS per position) ----
    unsigned key[NQ];
    float ce = 0.0f, bxs = 0.0f;
    int np = 0;
#pragma unroll
    for (int q = 0; q < NQ; q++) {
        const int p = tid + q * NT;
        const bool valid = (q < NQ - 1) || (p < P);
        key[q] = valid ? __ldg(&g_negkey[b * P + p]) : 0u;
        unsigned char mb = valid ? __ldg(&g_mbyte[b * P + p]) : 0;
        unsigned char ov = valid ? s_ovr[p] : 0;
        if (ov) mb = ov;                          // override wins
        const int mg  = mb & 15;
        const int pos = mb >> 7;
        if (pos) {
            np++;
            float bg = __uint_as_float(key[q]);
            key[q] = 0u;                          // exclude from hard-neg pool
            const float* rowp = logits + ((size_t)(b * P + p)) * C;
            float x0 = __ldg(rowp);
            float xl = __ldg(rowp + glab[mg]);
            ce += bg + x0 - xl;                   // = lse - x[lab]

            float4 pv = __ldg((const float4*)priors + p);
            float bx0 = gx0[mg], by0 = gy0[mg], bx1 = gx1[mg], by1 = gy1[mg];
            float t0 = ((bx0 + bx1) * 0.5f - pv.x) / (0.1f * pv.z);
            float t1 = ((by0 + by1) * 0.5f - pv.y) / (0.1f * pv.w);
            float t2 = __logf((bx1 - bx0) / pv.z) / 0.2f;
            float t3 = __logf((by1 - by0) / pv.w) / 0.2f;
            float4 br = __ldg((const float4*)box_reg + (b * P + p));
            float d0 = fabsf(br.x - t0), d1 = fabsf(br.y - t1);
            float d2 = fabsf(br.z - t2), d3 = fabsf(br.w - t3);
            bxs += (d0 < 1.0f) ? 0.5f * d0 * d0 : d0 - 0.5f;
            bxs += (d1 < 1.0f) ? 0.5f * d1 * d1 : d1 - 0.5f;
            bxs += (d2 < 1.0f) ? 0.5f * d2 * d2 : d2 - 0.5f;
            bxs += (d3 < 1.0f) ? 0.5f * d3 * d3 : d3 - 0.5f;
        }
    }
    // block reduction (ce, box, np)
#pragma unroll
    for (int o = 16; o > 0; o >>= 1) {
        ce  += __shfl_down_sync(0xffffffffu, ce, o);
        bxs += __shfl_down_sync(0xffffffffu, bxs, o);
        np  += __shfl_down_sync(0xffffffffu, np, o);
    }
    if (lane == 0) { wsf[warp] = ce; wsf2[warp] = bxs; wsi[warp] = np; }
    __syncthreads();
    if (warp == 0) {
        float c2 = wsf[lane], b2 = wsf2[lane];
        int n2 = wsi[lane];
#pragma unroll
        for (int o = 16; o > 0; o >>= 1) {
            c2 += __shfl_down_sync(0xffffffffu, c2, o);
            b2 += __shfl_down_sync(0xffffffffu, b2, o);
            n2 += __shfl_down_sync(0xffffffffu, n2, o);
        }
        if (lane == 0) {
            int k = n2 * 3; if (k > P) k = P;
            sh_k = k; sh_ce = c2;
            g_batch_box[b] = b2;
            g_batch_np[b]  = n2;
        }
    }
    __syncthreads();
    int k = sh_k;

    float cls = sh_ce;
    if (k > 0) {
        // =================== pass 1: bits [31:20] =====================
        for (int i = tid; i < 4096; i += NT) hist[i] = 0;
        __syncthreads();
#pragma unroll
        for (int q = 0; q < NQ; q++) {
            const bool valid = (q < NQ - 1) || (tid + q * NT < P);
            unsigned bkt = valid ? (key[q] >> 20) : 0xFFFFFFFFu;
            unsigned mm = __match_any_sync(0xffffffffu, bkt);
            if (valid && ((int)(__ffs(mm) - 1) == lane))
                atomicAdd(&hist[bkt], __popc(mm));
        }
        __syncthreads();
        {   // select bucket (cw = 16)
            const int cw = 16;
            int cs = 0;
            if (tid < 256)
                for (int i = 0; i < cw; i++) cs += hist[tid * cw + i];
            int v = cs;
#pragma unroll
            for (int o = 1; o < 32; o <<= 1) {
                int u = __shfl_down_sync(0xffffffffu, v, o);
                if (lane + o < 32) v += u;
            }
            if (tid < 256 && lane == 0) wsi[warp] = v;
            __syncthreads();
            if (tid < 256) {
                int off = 0;
                for (int w2 = warp + 1; w2 < 8; w2++) off += wsi[w2];
                suf[tid] = v + off;
            }
            __syncthreads();
            if (tid < 256) {
                int running = suf[tid] - cs;
                for (int i = cw - 1; i >= 0; i--) {
                    int c = hist[tid * cw + i];
                    if (c > 0 && running < k && running + c >= k) {
                        f_bucket = tid * cw + i;
                        f_above  = running;
                    }
                    running += c;
                }
            }
            __syncthreads();
        }
        const unsigned bkt1 = (unsigned)f_bucket;
        k -= f_above;
        __syncthreads();

        // =================== pass 2: bits [19:8] ======================
        for (int i = tid; i < 4096; i += NT) hist[i] = 0;
        __syncthreads();
#pragma unroll
        for (int q = 0; q < NQ; q++) {
            const bool valid = (q < NQ - 1) || (tid + q * NT < P);
            const bool act = valid && ((key[q] >> 20) == bkt1);
            unsigned bkt = act ? ((key[q] >> 8) & 0xFFF) : 0xFFFFFFFFu;
            unsigned mm = __match_any_sync(0xffffffffu, bkt);
            if (act && ((int)(__ffs(mm) - 1) == lane))
                atomicAdd(&hist[bkt], __popc(mm));
        }
        __syncthreads();
        {
            const int cw = 16;
            int cs = 0;
            if (tid < 256)
                for (int i = 0; i < cw; i++) cs += hist[tid * cw + i];
            int v = cs;
#pragma unroll
            for (int o = 1; o < 32; o <<= 1) {
                int u = __shfl_down_sync(0xffffffffu, v, o);
                if (lane + o < 32) v += u;
            }
            if (tid < 256 && lane == 0) wsi[warp] = v;
            __syncthreads();
            if (tid < 256) {
                int off = 0;
                for (int w2 = warp + 1; w2 < 8; w2++) off += wsi[w2];
                suf[tid] = v + off;
            }
            __syncthreads();
            if (tid < 256) {
                int running = suf[tid] - cs;
                for (int i = cw - 1; i >= 0; i--) {
                    int c = hist[tid * cw + i];
                    if (c > 0 && running < k && running + c >= k) {
                        f_bucket = tid * cw + i;
                        f_above  = running;
                    }
                    running += c;
                }
            }
            __syncthreads();
        }
        const unsigned prefix24 = (bkt1 << 12) | (unsigned)f_bucket;
        k -= f_above;                                   // rank within 24-bit bucket
        __syncthreads();

        // ============ candidate gather (keys sharing 24-bit prefix) ===
#pragma unroll
        for (int q = 0; q < NQ; q++) {
            const bool valid = (q < NQ - 1) || (tid + q * NT < P);
            if (valid && (key[q] >> 8) == prefix24) {
                int idx = atomicAdd(&cand_cnt, 1);
                if (idx < 32) cand[idx] = key[q];
            }
        }
        __syncthreads();

        if (cand_cnt <= 32) {
            if (warp == 0) {
                const int m = cand_cnt;
                unsigned ci = (lane < m) ? cand[lane] : 0u;
                int gt = 0, eq = 0;
#pragma unroll
                for (int j = 0; j < 32; j++) {
                    unsigned cj = __shfl_sync(0xffffffffu, ci, j);
                    if (lane < m && j < m) {
                        gt += (cj > ci);
                        eq += (cj == ci);
                    }
                }
                if (lane < m && gt < k && gt + eq >= k) {
                    sh_thr  = ci;
                    sh_kres = k - gt;
                }
            }
            __syncthreads();
        } else {
            // fallback: generic 8-bit pass
            for (int i = tid; i < 256; i += NT) hist[i] = 0;
            __syncthreads();
#pragma unroll
            for (int q = 0; q < NQ; q++) {
                const bool valid = (q < NQ - 1) || (tid + q * NT < P);
                const bool act = valid && ((key[q] >> 8) == prefix24);
                unsigned bkt = act ? (key[q] & 0xFF) : 0xFFFFFFFFu;
                unsigned mm = __match_any_sync(0xffffffffu, bkt);
                if (act && ((int)(__ffs(mm) - 1) == lane))
                    atomicAdd(&hist[bkt], __popc(mm));
            }
            __syncthreads();
            {
                int cs = 0;
                if (tid < 256) cs = hist[tid];
                int v = cs;
#pragma unroll
                for (int o = 1; o < 32; o <<= 1) {
                    int u = __shfl_down_sync(0xffffffffu, v, o);
                    if (lane + o < 32) v += u;
                }
                if (tid < 256 && lane == 0) wsi[warp] = v;
                __syncthreads();
                if (tid < 256) {
                    int off = 0;
                    for (int w2 = warp + 1; w2 < 8; w2++) off += wsi[w2];
                    suf[tid] = v + off;
                }
                __syncthreads();
                if (tid < 256) {
                    int running = suf[tid] - cs;
                    if (cs > 0 && running < k && running + cs >= k) {
                        f_bucket = tid;
                        f_above  = running;
                    }
                }
                __syncthreads();
            }
            if (tid == 0) {
                sh_thr  = (prefix24 << 8) | (unsigned)f_bucket;
                sh_kres = k - f_above;
            }
            __syncthreads();
        }

        // ============ final: sum strictly-greater + residual ties =====
        const unsigned thr = sh_thr;
        float ss = 0.0f;
#pragma unroll
        for (int q = 0; q < NQ; q++) {
            const bool valid = (q < NQ - 1) || (tid + q * NT < P);
            if (valid && key[q] > thr) ss += __uint_as_float(key[q]);
        }
#pragma unroll
        for (int o = 16; o > 0; o >>= 1) ss += __shfl_down_sync(0xffffffffu, ss, o);
        if (lane == 0) wsf[warp] = ss;
        __syncthreads();
        if (warp == 0) {
            float s2 = wsf[lane];
#pragma unroll
            for (int o = 16; o > 0; o >>= 1) s2 += __shfl_down_sync(0xffffffffu, s2, o);
            if (lane == 0) wsf[0] = s2;
        }
        __syncthreads();
        cls += wsf[0] + (float)sh_kres * __uint_as_float(thr);
    }

    if (tid == 0) {
        g_batch_cls[b] = cls;
        __threadfence();
        int v = atomicAdd(&g_done, 1);
        sh_last = (v == B - 1) ? 1 : 0;
    }
    __syncthreads();

    // ---- last-finishing block: finalize ----
    if (sh_last) {
        float box = 0.0f, ctot = 0.0f; int npos = 0;
        for (int i = tid; i < B; i += NT) {
            box  += *(volatile float*)&g_batch_box[i];
            ctot += *(volatile float*)&g_batch_cls[i];
            npos += *(volatile int*)&g_batch_np[i];
        }
#pragma unroll
        for (int o = 16; o > 0; o >>= 1) {
            box  += __shfl_down_sync(0xffffffffu, box, o);
            ctot += __shfl_down_sync(0xffffffffu, ctot, o);
            npos += __shfl_down_sync(0xffffffffu, npos, o);
        }
        if (lane == 0) { wsf[warp] = box; wsf2[warp] = ctot; wsi[warp] = npos; }
        __syncthreads();
        if (warp == 0) {
            float b2 = wsf[lane], c2 = wsf2[lane];
            int n2 = wsi[lane];
#pragma unroll
            for (int o = 16; o > 0; o >>= 1) {
                b2 += __shfl_down_sync(0xffffffffu, b2, o);
                c2 += __shfl_down_sync(0xffffffffu, c2, o);
                n2 += __shfl_down_sync(0xffffffffu, n2, o);
            }
            if (lane == 0) {
                float inv = 1.0f / (float)n2;
                out[0] = b2 * inv;
                out[1] = c2 * inv;
                g_done = 0;                              // self-reset for replay
            }
        }
    }
}

// =====================================================================
extern "C" void kernel_launch(void* const* d_in, const int* in_sizes, int n_in,
                              void* d_out, int out_size)
{
    const float* priors = (const float*)d_in[0];
    const float* logits = (const float*)d_in[1];
    const float* boxreg = (const float*)d_in[2];
    const float* gtb    = (const float*)d_in[3];
    const int*   gtl    = (const int*)d_in[4];

    const int P = in_sizes[0] / 4;
    const int B = in_sizes[2] / (4 * P);
    const int C = in_sizes[1] / (B * P);
    const int G = in_sizes[4] / B;

    const int nTiles = (P + TILE - 1) / TILE;
    const int nblk   = (P + SM_ROWS - 1) / SM_ROWS;
    const int nMatch = B * nTiles;

    fused_ms<<<nMatch + B * nblk, 256>>>(logits, priors, gtb,
                                         P, C, G, nMatch, nTiles, nblk);

    apply_topk<<<B, 1024>>>((float*)d_out, logits, priors, boxreg, gtb, gtl,
                            P, C, G, B);
}